// round 15
// baseline (speedup 1.0000x reference)
#include <cuda_runtime.h>
#include <cuda_bf16.h>
#include <cstdint>

// Problem dims
#define BB    256
#define NIN   64
#define DIN   128
#define MM    32
#define DOUTD 128
#define MD    (MM * DOUTD)          // 4096
#define VPB   (NIN * MD)            // 262144
#define SCALE 0.08838834764831845f  // 1/sqrt(128)
#define NCHUNK 4
#define NPC   (NIN / NCHUNK)        // 16

// -------- device scratch ---------------------------------------------------
__device__ float g_votes[(size_t)BB * NIN * MM * DOUTD];     // 256 MiB
__device__ float g_ncv[(size_t)BB * MD];                     // 4 MiB
__device__ float g_part[(size_t)BB * NCHUNK * MD];           // 16 MiB
__device__ float g_xt[(size_t)BB * NIN * DIN];               // 8 MiB (tf32-rounded x)

// -------- helpers ------------------------------------------------------------
__device__ __forceinline__ void cp_async16(void* smem_dst, const void* gmem_src) {
    unsigned s = (unsigned)__cvta_generic_to_shared(smem_dst);
    asm volatile("cp.async.cg.shared.global [%0], [%1], 16;\n" :: "r"(s), "l"(gmem_src));
}
__device__ __forceinline__ void cp_commit() { asm volatile("cp.async.commit_group;\n"); }
template <int N> __device__ __forceinline__ void cp_wait() {
    asm volatile("cp.async.wait_group %0;\n" :: "n"(N));
}
__device__ __forceinline__ float cvt_tf32(float f) {
    uint32_t o;
    asm("cvt.rna.tf32.f32 %0, %1;" : "=r"(o) : "f"(f));
    return __uint_as_float(o);
}
__device__ __forceinline__ uint32_t tf32_bits(float f) {
    uint32_t o;
    asm("cvt.rna.tf32.f32 %0, %1;" : "=r"(o) : "f"(f));
    return o;
}

#define MMA_TF32(c0, c1, c2, c3, a0, a1, a2, a3, b0, b1)                       \
    asm volatile(                                                              \
        "mma.sync.aligned.m16n8k8.row.col.f32.tf32.tf32.f32 "                  \
        "{%0,%1,%2,%3}, {%4,%5,%6,%7}, {%8,%9}, {%0,%1,%2,%3};\n"              \
        : "+f"(c0), "+f"(c1), "+f"(c2), "+f"(c3)                               \
        : "r"(a0), "r"(a1), "r"(a2), "r"(a3), "r"(b0), "r"(b1))

#define LDSM_X4(r0, r1, r2, r3, addr)                                          \
    asm volatile(                                                              \
        "ldmatrix.sync.aligned.m8n8.x4.shared.b16 {%0,%1,%2,%3}, [%4];"        \
        : "=r"(r0), "=r"(r1), "=r"(r2), "=r"(r3) : "r"(addr))

// ===========================================================================
// K0: round x to tf32 (8 MiB, ~3 us). W rounded in-register inside votes.
// ===========================================================================
#define XF4 ((BB * NIN * DIN) / 4)        // 524,288

__global__ __launch_bounds__(256) void prep_x_kernel(const float* __restrict__ x) {
    const int idx = blockIdx.x * 256 + threadIdx.x;
    float4 v = ((const float4*)x)[idx];
    v.x = cvt_tf32(v.x); v.y = cvt_tf32(v.y); v.z = cvt_tf32(v.z); v.w = cvt_tf32(v.w);
    ((float4*)g_xt)[idx] = v;
}

// ===========================================================================
// K1: votes via tf32 tensor cores, n-loop with fused ncv0.
// 128 threads / 4 warps (2m x 2n), warp tile 32x64, block 64(b) x 128(j).
// grid (32, 4) = 128 blocks. Crossbar-byte-bound fix: dup A=2x, B=2x.
// B pitch 136: 4 t-groups on disjoint bank octets (conflict-free B loads).
// ===========================================================================
#define BMV 64
#define BNV 128
#define APITCH 132
#define BPITCH 136
#define STAGEF (BMV * APITCH + DIN * BPITCH)             // 25,856 floats
#define VSMEM  (2 * STAGEF * 4)                          // 206,848 B

__global__ __launch_bounds__(128) void votes_tf32_kernel(const float* __restrict__ W) {
    extern __shared__ float sm_[];
    float* Abuf0 = sm_;
    float* Bbuf0 = sm_ + BMV * APITCH;
    float* Abuf1 = Bbuf0 + DIN * BPITCH;
    float* Bbuf1 = Abuf1 + BMV * APITCH;

    const int j0 = blockIdx.x * BNV;
    const int b0 = blockIdx.y * BMV;
    const int tid  = threadIdx.x;
    const int lane = tid & 31;
    const int warp = tid >> 5;       // 0..3
    const int warp_m = warp >> 1;    // 0..1 (32 rows each)
    const int warp_n = warp & 1;     // 0..1 (64 cols each)
    const int g = lane >> 2;         // 0..7
    const int t = lane & 3;          // 0..3

    // ldmatrix lane addressing (as R13)
    const int q  = lane >> 3;
    const int r8 = lane & 7;
    const int a_row = warp_m * 32 + (q & 1) * 8 + r8;
    const int a_kq  = (q >> 1) * 4;
    const uint32_t a0addr = (uint32_t)__cvta_generic_to_shared(Abuf0)
                          + (uint32_t)(a_row * APITCH + a_kq) * 4u;
    const uint32_t a1addr = (uint32_t)__cvta_generic_to_shared(Abuf1)
                          + (uint32_t)(a_row * APITCH + a_kq) * 4u;

    const float* xbase = g_xt + (size_t)b0 * (NIN * DIN);
    const float* wbase = W + j0;

    auto issue_tile = [&](float* Ad, float* Bd, int n) {
        const float* xs = xbase + n * DIN;
        #pragma unroll
        for (int i = 0; i < 16; ++i) {            // A: 64 rows x 32 chunks
            int id = tid + i * 128;
            int row = id >> 5, c = id & 31;
            cp_async16(Ad + row * APITCH + c * 4, xs + (size_t)row * (NIN * DIN) + c * 4);
        }
        const float* ws = wbase + (size_t)n * (DIN * MD);
        #pragma unroll
        for (int i = 0; i < 32; ++i) {            // B: 128 rows x 32 chunks
            int id = tid + i * 128;
            int kr = id >> 5, c = id & 31;
            cp_async16(Bd + kr * BPITCH + c * 4, ws + (size_t)kr * MD + c * 4);
        }
        cp_commit();
    };

    float c[2][8][4];
    float ncv[2][8][4];
    #pragma unroll
    for (int mt = 0; mt < 2; ++mt)
        #pragma unroll
        for (int nt = 0; nt < 8; ++nt)
            #pragma unroll
            for (int qq = 0; qq < 4; ++qq) { c[mt][nt][qq] = 0.f; ncv[mt][nt][qq] = 0.f; }

    issue_tile(Abuf0, Bbuf0, 0);

    for (int n = 0; n < NIN; ++n) {
        float* Bb = (n & 1) ? Bbuf1 : Bbuf0;
        const uint32_t aaddr = (n & 1) ? a1addr : a0addr;
        if (n + 1 < NIN) {
            issue_tile((n & 1) ? Abuf0 : Abuf1, (n & 1) ? Bbuf0 : Bbuf1, n + 1);
            cp_wait<1>();
        } else {
            cp_wait<0>();
        }
        __syncthreads();

        // ---- mainloop: 16 k-steps of 8
        #pragma unroll
        for (int ks = 0; ks < 16; ++ks) {
            const int kb = ks * 8;
            uint32_t a[2][4];
            LDSM_X4(a[0][0], a[0][1], a[0][2], a[0][3], aaddr + kb * 4);
            LDSM_X4(a[1][0], a[1][1], a[1][2], a[1][3],
                    aaddr + (16 * APITCH + kb) * 4);
            #pragma unroll
            for (int nt = 0; nt < 8; ++nt) {
                const int j = warp_n * 64 + nt * 8 + g;
                const float* bp = Bb + (kb + t) * BPITCH + j;
                uint32_t bb0 = tf32_bits(bp[0]);
                uint32_t bb1 = tf32_bits(bp[4 * BPITCH]);
                #pragma unroll
                for (int mt = 0; mt < 2; ++mt) {
                    MMA_TF32(c[mt][nt][0], c[mt][nt][1], c[mt][nt][2], c[mt][nt][3],
                             a[mt][0], a[mt][1], a[mt][2], a[mt][3], bb0, bb1);
                }
            }
        }

        // ---- epilogue: write votes tile, accumulate ncv, reset c
        #pragma unroll
        for (int mt = 0; mt < 2; ++mt) {
            const int row = warp_m * 32 + mt * 16 + g;
            float* vp = g_votes + (size_t)(b0 + row) * VPB + (size_t)n * MD + j0;
            #pragma unroll
            for (int nt = 0; nt < 8; ++nt) {
                const int col = warp_n * 64 + nt * 8 + 2 * t;
                *(float2*)(vp + col)           = make_float2(c[mt][nt][0], c[mt][nt][1]);
                *(float2*)(vp + 8 * VPB + col) = make_float2(c[mt][nt][2], c[mt][nt][3]);
                ncv[mt][nt][0] += c[mt][nt][0]; c[mt][nt][0] = 0.f;
                ncv[mt][nt][1] += c[mt][nt][1]; c[mt][nt][1] = 0.f;
                ncv[mt][nt][2] += c[mt][nt][2]; c[mt][nt][2] = 0.f;
                ncv[mt][nt][3] += c[mt][nt][3]; c[mt][nt][3] = 0.f;
            }
        }
        __syncthreads();   // protect smem buffers before next prefetch overwrite
    }

    // ---- write ncv0 = (1/M) * sum_n votes (fused)
    #pragma unroll
    for (int mt = 0; mt < 2; ++mt) {
        const int row = warp_m * 32 + mt * 16 + g;
        float* np = g_ncv + (size_t)(b0 + row) * MD + j0;
        #pragma unroll
        for (int nt = 0; nt < 8; ++nt) {
            const int col = warp_n * 64 + nt * 8 + 2 * t;
            *(float2*)(np + col) =
                make_float2(ncv[mt][nt][0] * (1.0f / MM), ncv[mt][nt][1] * (1.0f / MM));
            *(float2*)(np + 8 * MD + col) =
                make_float2(ncv[mt][nt][2] * (1.0f / MM), ncv[mt][nt][3] * (1.0f / MM));
        }
    }
}

// ===========================================================================
// K3: routing iteration, n-chunked. grid (BB, NCHUNK=4). (R13 verbatim.)
// ===========================================================================
#define ITER_SMEM ((MD + 2 * MD + 32) * 4)   // 49,280 B

__global__ __launch_bounds__(256) void route_iter_kernel(const float* __restrict__ act,
                                                         int is_final,
                                                         float* __restrict__ out_q,
                                                         float* __restrict__ out_route) {
    extern __shared__ float smem[];
    float* s_ncv   = smem;
    float* s_votes = smem + MD;
    float* s_q     = smem + 3 * MD;

    const int b     = blockIdx.x;
    const int chunk = blockIdx.y;
    const int n0    = chunk * NPC;
    const int tid  = threadIdx.x;
    const int lane = tid & 31;
    const int warp = tid >> 5;

    #pragma unroll 4
    for (int i = tid; i < MD; i += 256) s_ncv[i] = g_ncv[(size_t)b * MD + i];

    float4 acc0 = make_float4(0.f, 0.f, 0.f, 0.f);
    float4 acc1 = make_float4(0.f, 0.f, 0.f, 0.f);
    float4 acc2 = make_float4(0.f, 0.f, 0.f, 0.f);
    float4 acc3 = make_float4(0.f, 0.f, 0.f, 0.f);

    const float* vbase = g_votes + (size_t)b * VPB + (size_t)n0 * MD;

    #pragma unroll
    for (int i = tid * 4; i < MD; i += 1024) cp_async16(&s_votes[i], vbase + i);
    cp_commit();

    for (int nn = 0; nn < NPC; ++nn) {
        const int n = n0 + nn;
        const int buf = (nn & 1) * MD;
        if (nn + 1 < NPC) {
            const float* src = vbase + (size_t)(nn + 1) * MD;
            const int nbuf = ((nn + 1) & 1) * MD;
            #pragma unroll
            for (int i = tid * 4; i < MD; i += 1024) cp_async16(&s_votes[nbuf + i], src + i);
            cp_commit();
            cp_wait<1>();
        } else {
            cp_wait<0>();
        }
        __syncthreads();

        #pragma unroll
        for (int j = 0; j < 4; ++j) {
            const int m = warp * 4 + j;
            const float* vr = &s_votes[buf + m * DOUTD];
            const float* cr = &s_ncv[m * DOUTD];
            float p = vr[lane]      * cr[lane]
                    + vr[lane + 32] * cr[lane + 32]
                    + vr[lane + 64] * cr[lane + 64]
                    + vr[lane + 96] * cr[lane + 96];
            p += __shfl_xor_sync(0xffffffffu, p, 16);
            p += __shfl_xor_sync(0xffffffffu, p, 8);
            p += __shfl_xor_sync(0xffffffffu, p, 4);
            p += __shfl_xor_sync(0xffffffffu, p, 2);
            p += __shfl_xor_sync(0xffffffffu, p, 1);
            if (lane == 0) s_q[m] = p;
        }
        __syncthreads();

        if (warp == 0) {
            float v = s_q[lane] * SCALE;
            float mx = v;
            #pragma unroll
            for (int o = 16; o > 0; o >>= 1) mx = fmaxf(mx, __shfl_xor_sync(0xffffffffu, mx, o));
            float e = expf(v - mx);
            float sm = e;
            #pragma unroll
            for (int o = 16; o > 0; o >>= 1) sm += __shfl_xor_sync(0xffffffffu, sm, o);
            s_q[lane] = e / sm;
        }
        __syncthreads();

        const float wa = act[b * NIN + n];
        {
            const int i0 = tid * 4;
            float q0 = s_q[i0 >> 7] * wa;
            float q1 = s_q[(i0 + 1024) >> 7] * wa;
            float q2 = s_q[(i0 + 2048) >> 7] * wa;
            float q3 = s_q[(i0 + 3072) >> 7] * wa;
            float4 v0 = *(const float4*)&s_votes[buf + i0];
            float4 v1 = *(const float4*)&s_votes[buf + i0 + 1024];
            float4 v2 = *(const float4*)&s_votes[buf + i0 + 2048];
            float4 v3 = *(const float4*)&s_votes[buf + i0 + 3072];
            v0.x *= q0; v0.y *= q0; v0.z *= q0; v0.w *= q0;
            v1.x *= q1; v1.y *= q1; v1.z *= q1; v1.w *= q1;
            v2.x *= q2; v2.y *= q2; v2.z *= q2; v2.w *= q2;
            v3.x *= q3; v3.y *= q3; v3.z *= q3; v3.w *= q3;
            acc0.x += v0.x; acc0.y += v0.y; acc0.z += v0.z; acc0.w += v0.w;
            acc1.x += v1.x; acc1.y += v1.y; acc1.z += v1.z; acc1.w += v1.w;
            acc2.x += v2.x; acc2.y += v2.y; acc2.z += v2.z; acc2.w += v2.w;
            acc3.x += v3.x; acc3.y += v3.y; acc3.z += v3.z; acc3.w += v3.w;
            if (is_final) {
                float* rp = out_route + (size_t)b * VPB + (size_t)n * MD;
                *(float4*)(rp + i0)        = v0;
                *(float4*)(rp + i0 + 1024) = v1;
                *(float4*)(rp + i0 + 2048) = v2;
                *(float4*)(rp + i0 + 3072) = v3;
            }
        }
        if (is_final && tid < MM)
            out_q[(size_t)b * (NIN * MM) + n * MM + tid] = s_q[tid];
        __syncthreads();
    }

    float* pp = g_part + ((size_t)b * NCHUNK + chunk) * MD;
    const int i0 = tid * 4;
    *(float4*)(pp + i0)        = acc0;
    *(float4*)(pp + i0 + 1024) = acc1;
    *(float4*)(pp + i0 + 2048) = acc2;
    *(float4*)(pp + i0 + 3072) = acc3;
}

// ===========================================================================
// K4: reduce partials -> g_ncv (to_out=0) or out_ncv (to_out=1).
// ===========================================================================
__global__ __launch_bounds__(256) void reduce_kernel(int to_out, float* __restrict__ out_ncv) {
    float* dst = to_out ? out_ncv : g_ncv;
    const int idx = blockIdx.x * 256 + threadIdx.x;
    const int b  = idx >> 10;
    const int r4 = (idx & 1023) * 4;
    const float* pp = g_part + (size_t)b * NCHUNK * MD + r4;
    float4 s = make_float4(0.f, 0.f, 0.f, 0.f);
    #pragma unroll 4
    for (int c = 0; c < NCHUNK; ++c) {
        float4 v = *(const float4*)(pp + (size_t)c * MD);
        s.x += v.x; s.y += v.y; s.z += v.z; s.w += v.w;
    }
    *(float4*)(dst + (size_t)b * MD + r4) = s;
}

// ===========================================================================
// launch
// ===========================================================================
extern "C" void kernel_launch(void* const* d_in, const int* in_sizes, int n_in,
                              void* d_out, int out_size) {
    const float* x   = (const float*)d_in[0];
    const float* act = (const float*)d_in[1];
    const float* W   = (const float*)d_in[2];

    float* out       = (float*)d_out;
    float* out_ncv   = out;
    float* out_q     = out + (size_t)BB * MM * DOUTD;
    float* out_route = out_q + (size_t)BB * NIN * MM;

    cudaFuncSetAttribute(votes_tf32_kernel, cudaFuncAttributeMaxDynamicSharedMemorySize, VSMEM);
    cudaFuncSetAttribute(route_iter_kernel, cudaFuncAttributeMaxDynamicSharedMemorySize, ITER_SMEM);

    prep_x_kernel<<<XF4 / 256, 256>>>(x);
    votes_tf32_kernel<<<dim3(MD / BNV, BB / BMV), 128, VSMEM>>>(W);

    route_iter_kernel<<<dim3(BB, NCHUNK), 256, ITER_SMEM>>>(act, 0, nullptr, nullptr);
    reduce_kernel<<<(BB * MD / 4) / 256, 256>>>(0, nullptr);
    route_iter_kernel<<<dim3(BB, NCHUNK), 256, ITER_SMEM>>>(act, 0, nullptr, nullptr);
    reduce_kernel<<<(BB * MD / 4) / 256, 256>>>(0, nullptr);
    route_iter_kernel<<<dim3(BB, NCHUNK), 256, ITER_SMEM>>>(act, 1, out_q, out_route);
    reduce_kernel<<<(BB * MD / 4) / 256, 256>>>(1, out_ncv);
}

// round 16
// speedup vs baseline: 1.0790x; 1.0790x over previous
#include <cuda_runtime.h>
#include <cuda_fp16.h>
#include <cstdint>

// Problem dims
#define BB    256
#define NIN   64
#define DIN   128
#define MM    32
#define DOUTD 128
#define MD    (MM * DOUTD)          // 4096
#define VPB   (NIN * MD)            // 262144
#define SCALE 0.08838834764831845f  // 1/sqrt(128)
#define NCHUNK 4
#define NPC   (NIN / NCHUNK)        // 16

// -------- device scratch ---------------------------------------------------
__device__ float g_votes[(size_t)BB * NIN * MM * DOUTD];     // 256 MiB
__device__ float g_ncv[(size_t)BB * MD];                     // 4 MiB
__device__ float g_part[(size_t)BB * NCHUNK * MD];           // 16 MiB
__device__ __half g_xh[(size_t)BB * NIN * DIN];              // 4 MiB (fp16 x)

// -------- helpers ------------------------------------------------------------
__device__ __forceinline__ void cp_async16(void* smem_dst, const void* gmem_src) {
    unsigned s = (unsigned)__cvta_generic_to_shared(smem_dst);
    asm volatile("cp.async.cg.shared.global [%0], [%1], 16;\n" :: "r"(s), "l"(gmem_src));
}
__device__ __forceinline__ void cp_async16s(uint32_t saddr, const void* gmem_src) {
    asm volatile("cp.async.cg.shared.global [%0], [%1], 16;\n" :: "r"(saddr), "l"(gmem_src));
}
__device__ __forceinline__ void cp_commit() { asm volatile("cp.async.commit_group;\n"); }
template <int N> __device__ __forceinline__ void cp_wait() {
    asm volatile("cp.async.wait_group %0;\n" :: "n"(N));
}

// pack two f32 -> f16x2 (lo = second operand)
#define F16X2(d, hi, lo) \
    asm("cvt.rn.f16x2.f32 %0, %1, %2;" : "=r"(d) : "f"(hi), "f"(lo))

#define MMA_F16(c0, c1, c2, c3, a0, a1, a2, a3, b0, b1)                        \
    asm volatile(                                                              \
        "mma.sync.aligned.m16n8k16.row.col.f32.f16.f16.f32 "                   \
        "{%0,%1,%2,%3}, {%4,%5,%6,%7}, {%8,%9}, {%0,%1,%2,%3};\n"              \
        : "+f"(c0), "+f"(c1), "+f"(c2), "+f"(c3)                               \
        : "r"(a0), "r"(a1), "r"(a2), "r"(a3), "r"(b0), "r"(b1))

#define LDSM_X4(r0, r1, r2, r3, addr)                                          \
    asm volatile(                                                              \
        "ldmatrix.sync.aligned.m8n8.x4.shared.b16 {%0,%1,%2,%3}, [%4];"        \
        : "=r"(r0), "=r"(r1), "=r"(r2), "=r"(r3) : "r"(addr))

// ===========================================================================
// K0: convert x to fp16 (k-contiguous). 8 MiB read + 4 MiB write, ~3 us.
// ===========================================================================
#define XF4 ((BB * NIN * DIN) / 4)        // 524,288

__global__ __launch_bounds__(256) void prep_x_kernel(const float* __restrict__ x) {
    const int idx = blockIdx.x * 256 + threadIdx.x;
    float4 v = ((const float4*)x)[idx];
    uint2 o;
    F16X2(o.x, v.y, v.x);   // mem order: lo half = k, hi = k+1
    F16X2(o.y, v.w, v.z);
    ((uint2*)g_xh)[idx] = o;
}

// ===========================================================================
// K1: votes via fp16 m16n8k16 tensor cores, n-loop with fused ncv0.
// 256 threads / 8 warps (4m x 2n), warp tile 32x32, block 128(b) x 64(j),
// grid (64, 2). A: fp16 smem rows (256B + 16B pad), ldmatrix.x4 fragments.
// B: raw fp32 smem, packed to f16x2 in registers (cvt.rn.f16x2.f32).
// ===========================================================================
#define BMV 128
#define BNV 64
#define APB 272                     // bytes per A row (256 data + 16 pad)
#define BPITCH 72                   // floats per B row
#define ABYTES (BMV * APB)          // 34,816
#define BBYTES (DIN * BPITCH * 4)   // 36,864
#define STG_B  (ABYTES + BBYTES)    // 71,680
#define VSMEM  (2 * STG_B)          // 143,360 B

__global__ __launch_bounds__(256) void votes_f16_kernel(const float* __restrict__ W) {
    extern __shared__ char sm_[];
    char*  A0 = sm_;
    float* B0 = (float*)(sm_ + ABYTES);
    char*  A1 = sm_ + STG_B;
    float* B1 = (float*)(sm_ + STG_B + ABYTES);

    const int j0 = blockIdx.x * BNV;
    const int b0 = blockIdx.y * BMV;
    const int tid  = threadIdx.x;
    const int lane = tid & 31;
    const int warp = tid >> 5;
    const int warp_m = warp >> 1;    // 0..3 (32 rows each)
    const int warp_n = warp & 1;     // 0..1 (32 cols each)
    const int g = lane >> 2;         // 0..7
    const int t = lane & 3;          // 0..3

    // ldmatrix lane addressing: mat0=rows0-7/k0-7, mat1=rows8-15/k0-7,
    // mat2=rows0-7/k8-15, mat3=rows8-15/k8-15.
    const int lrow = ((lane >> 3) & 1) * 8 + (lane & 7);
    const int koff = (lane >> 4) * 16;   // bytes
    const uint32_t a0base = (uint32_t)__cvta_generic_to_shared(A0)
                          + (uint32_t)((warp_m * 32 + lrow) * APB + koff);
    const uint32_t a1base = (uint32_t)__cvta_generic_to_shared(A1)
                          + (uint32_t)((warp_m * 32 + lrow) * APB + koff);

    const __half* xbase = g_xh + (size_t)b0 * (NIN * DIN);
    const float*  wbase = W + j0;

    auto issue_tile = [&](char* Ad, float* Bd, int n) {
        const __half* xs = xbase + n * DIN;
        const uint32_t adst = (uint32_t)__cvta_generic_to_shared(Ad);
        #pragma unroll
        for (int i = 0; i < 8; ++i) {             // A: 128 rows x 16 chunks (16B)
            int id = tid + i * 256;
            int r = id >> 4, c = id & 15;
            cp_async16s(adst + (uint32_t)(r * APB + c * 16),
                        xs + (size_t)r * (NIN * DIN) + c * 8);
        }
        const float* ws = wbase + (size_t)n * (DIN * MD);
        #pragma unroll
        for (int i = 0; i < 8; ++i) {             // B: 128 rows x 16 chunks
            int id = tid + i * 256;
            int k = id >> 4, c = id & 15;
            cp_async16(Bd + k * BPITCH + c * 4, ws + (size_t)k * MD + c * 4);
        }
        cp_commit();
    };

    float c[2][4][4];
    float ncv[2][4][4];
    #pragma unroll
    for (int mt = 0; mt < 2; ++mt)
        #pragma unroll
        for (int nt = 0; nt < 4; ++nt)
            #pragma unroll
            for (int qq = 0; qq < 4; ++qq) { c[mt][nt][qq] = 0.f; ncv[mt][nt][qq] = 0.f; }

    issue_tile(A0, B0, 0);

    for (int n = 0; n < NIN; ++n) {
        float* Bb = (n & 1) ? B1 : B0;
        const uint32_t abase = (n & 1) ? a1base : a0base;
        if (n + 1 < NIN) {
            issue_tile((n & 1) ? A0 : A1, (n & 1) ? B0 : B1, n + 1);
            cp_wait<1>();
        } else {
            cp_wait<0>();
        }
        __syncthreads();

        // ---- mainloop: 8 k-steps of 16
        #pragma unroll
        for (int ks = 0; ks < 8; ++ks) {
            const int kb = ks * 16;             // fp32 k-row base for B
            uint32_t a[2][4];
            LDSM_X4(a[0][0], a[0][1], a[0][2], a[0][3], abase + ks * 32);
            LDSM_X4(a[1][0], a[1][1], a[1][2], a[1][3], abase + 16 * APB + ks * 32);
            #pragma unroll
            for (int nt = 0; nt < 4; ++nt) {
                const int j = warp_n * 32 + nt * 8 + g;
                const float* bp = Bb + (size_t)(kb + 2 * t) * BPITCH + j;
                float w0 = bp[0];
                float w1 = bp[BPITCH];
                float w2 = bp[8 * BPITCH];
                float w3 = bp[9 * BPITCH];
                uint32_t bb0, bb1;
                F16X2(bb0, w1, w0);             // {lo=k_even, hi=k_odd}
                F16X2(bb1, w3, w2);
                #pragma unroll
                for (int mt = 0; mt < 2; ++mt) {
                    MMA_F16(c[mt][nt][0], c[mt][nt][1], c[mt][nt][2], c[mt][nt][3],
                            a[mt][0], a[mt][1], a[mt][2], a[mt][3], bb0, bb1);
                }
            }
        }

        // ---- epilogue: write votes tile, accumulate ncv, reset c
        #pragma unroll
        for (int mt = 0; mt < 2; ++mt) {
            const int row = warp_m * 32 + mt * 16 + g;
            float* vp = g_votes + (size_t)(b0 + row) * VPB + (size_t)n * MD + j0;
            #pragma unroll
            for (int nt = 0; nt < 4; ++nt) {
                const int col = warp_n * 32 + nt * 8 + 2 * t;
                *(float2*)(vp + col)           = make_float2(c[mt][nt][0], c[mt][nt][1]);
                *(float2*)(vp + 8 * VPB + col) = make_float2(c[mt][nt][2], c[mt][nt][3]);
                ncv[mt][nt][0] += c[mt][nt][0]; c[mt][nt][0] = 0.f;
                ncv[mt][nt][1] += c[mt][nt][1]; c[mt][nt][1] = 0.f;
                ncv[mt][nt][2] += c[mt][nt][2]; c[mt][nt][2] = 0.f;
                ncv[mt][nt][3] += c[mt][nt][3]; c[mt][nt][3] = 0.f;
            }
        }
        __syncthreads();   // protect smem buffers before next prefetch overwrite
    }

    // ---- write ncv0 = (1/M) * sum_n votes (fused)
    #pragma unroll
    for (int mt = 0; mt < 2; ++mt) {
        const int row = warp_m * 32 + mt * 16 + g;
        float* np = g_ncv + (size_t)(b0 + row) * MD + j0;
        #pragma unroll
        for (int nt = 0; nt < 4; ++nt) {
            const int col = warp_n * 32 + nt * 8 + 2 * t;
            *(float2*)(np + col) =
                make_float2(ncv[mt][nt][0] * (1.0f / MM), ncv[mt][nt][1] * (1.0f / MM));
            *(float2*)(np + 8 * MD + col) =
                make_float2(ncv[mt][nt][2] * (1.0f / MM), ncv[mt][nt][3] * (1.0f / MM));
        }
    }
}

// ===========================================================================
// K3: routing iteration, n-chunked. grid (BB, NCHUNK=4). (R13 verbatim.)
// ===========================================================================
#define ITER_SMEM ((MD + 2 * MD + 32) * 4)   // 49,280 B

__global__ __launch_bounds__(256) void route_iter_kernel(const float* __restrict__ act,
                                                         int is_final,
                                                         float* __restrict__ out_q,
                                                         float* __restrict__ out_route) {
    extern __shared__ float smem[];
    float* s_ncv   = smem;
    float* s_votes = smem + MD;
    float* s_q     = smem + 3 * MD;

    const int b     = blockIdx.x;
    const int chunk = blockIdx.y;
    const int n0    = chunk * NPC;
    const int tid  = threadIdx.x;
    const int lane = tid & 31;
    const int warp = tid >> 5;

    #pragma unroll 4
    for (int i = tid; i < MD; i += 256) s_ncv[i] = g_ncv[(size_t)b * MD + i];

    float4 acc0 = make_float4(0.f, 0.f, 0.f, 0.f);
    float4 acc1 = make_float4(0.f, 0.f, 0.f, 0.f);
    float4 acc2 = make_float4(0.f, 0.f, 0.f, 0.f);
    float4 acc3 = make_float4(0.f, 0.f, 0.f, 0.f);

    const float* vbase = g_votes + (size_t)b * VPB + (size_t)n0 * MD;

    #pragma unroll
    for (int i = tid * 4; i < MD; i += 1024) cp_async16(&s_votes[i], vbase + i);
    cp_commit();

    for (int nn = 0; nn < NPC; ++nn) {
        const int n = n0 + nn;
        const int buf = (nn & 1) * MD;
        if (nn + 1 < NPC) {
            const float* src = vbase + (size_t)(nn + 1) * MD;
            const int nbuf = ((nn + 1) & 1) * MD;
            #pragma unroll
            for (int i = tid * 4; i < MD; i += 1024) cp_async16(&s_votes[nbuf + i], src + i);
            cp_commit();
            cp_wait<1>();
        } else {
            cp_wait<0>();
        }
        __syncthreads();

        #pragma unroll
        for (int j = 0; j < 4; ++j) {
            const int m = warp * 4 + j;
            const float* vr = &s_votes[buf + m * DOUTD];
            const float* cr = &s_ncv[m * DOUTD];
            float p = vr[lane]      * cr[lane]
                    + vr[lane + 32] * cr[lane + 32]
                    + vr[lane + 64] * cr[lane + 64]
                    + vr[lane + 96] * cr[lane + 96];
            p += __shfl_xor_sync(0xffffffffu, p, 16);
            p += __shfl_xor_sync(0xffffffffu, p, 8);
            p += __shfl_xor_sync(0xffffffffu, p, 4);
            p += __shfl_xor_sync(0xffffffffu, p, 2);
            p += __shfl_xor_sync(0xffffffffu, p, 1);
            if (lane == 0) s_q[m] = p;
        }
        __syncthreads();

        if (warp == 0) {
            float v = s_q[lane] * SCALE;
            float mx = v;
            #pragma unroll
            for (int o = 16; o > 0; o >>= 1) mx = fmaxf(mx, __shfl_xor_sync(0xffffffffu, mx, o));
            float e = expf(v - mx);
            float sm = e;
            #pragma unroll
            for (int o = 16; o > 0; o >>= 1) sm += __shfl_xor_sync(0xffffffffu, sm, o);
            s_q[lane] = e / sm;
        }
        __syncthreads();

        const float wa = act[b * NIN + n];
        {
            const int i0 = tid * 4;
            float q0 = s_q[i0 >> 7] * wa;
            float q1 = s_q[(i0 + 1024) >> 7] * wa;
            float q2 = s_q[(i0 + 2048) >> 7] * wa;
            float q3 = s_q[(i0 + 3072) >> 7] * wa;
            float4 v0 = *(const float4*)&s_votes[buf + i0];
            float4 v1 = *(const float4*)&s_votes[buf + i0 + 1024];
            float4 v2 = *(const float4*)&s_votes[buf + i0 + 2048];
            float4 v3 = *(const float4*)&s_votes[buf + i0 + 3072];
            v0.x *= q0; v0.y *= q0; v0.z *= q0; v0.w *= q0;
            v1.x *= q1; v1.y *= q1; v1.z *= q1; v1.w *= q1;
            v2.x *= q2; v2.y *= q2; v2.z *= q2; v2.w *= q2;
            v3.x *= q3; v3.y *= q3; v3.z *= q3; v3.w *= q3;
            acc0.x += v0.x; acc0.y += v0.y; acc0.z += v0.z; acc0.w += v0.w;
            acc1.x += v1.x; acc1.y += v1.y; acc1.z += v1.z; acc1.w += v1.w;
            acc2.x += v2.x; acc2.y += v2.y; acc2.z += v2.z; acc2.w += v2.w;
            acc3.x += v3.x; acc3.y += v3.y; acc3.z += v3.z; acc3.w += v3.w;
            if (is_final) {
                float* rp = out_route + (size_t)b * VPB + (size_t)n * MD;
                *(float4*)(rp + i0)        = v0;
                *(float4*)(rp + i0 + 1024) = v1;
                *(float4*)(rp + i0 + 2048) = v2;
                *(float4*)(rp + i0 + 3072) = v3;
            }
        }
        if (is_final && tid < MM)
            out_q[(size_t)b * (NIN * MM) + n * MM + tid] = s_q[tid];
        __syncthreads();
    }

    float* pp = g_part + ((size_t)b * NCHUNK + chunk) * MD;
    const int i0 = tid * 4;
    *(float4*)(pp + i0)        = acc0;
    *(float4*)(pp + i0 + 1024) = acc1;
    *(float4*)(pp + i0 + 2048) = acc2;
    *(float4*)(pp + i0 + 3072) = acc3;
}

// ===========================================================================
// K4: reduce partials -> g_ncv (to_out=0) or out_ncv (to_out=1).
// ===========================================================================
__global__ __launch_bounds__(256) void reduce_kernel(int to_out, float* __restrict__ out_ncv) {
    float* dst = to_out ? out_ncv : g_ncv;
    const int idx = blockIdx.x * 256 + threadIdx.x;
    const int b  = idx >> 10;
    const int r4 = (idx & 1023) * 4;
    const float* pp = g_part + (size_t)b * NCHUNK * MD + r4;
    float4 s = make_float4(0.f, 0.f, 0.f, 0.f);
    #pragma unroll 4
    for (int c = 0; c < NCHUNK; ++c) {
        float4 v = *(const float4*)(pp + (size_t)c * MD);
        s.x += v.x; s.y += v.y; s.z += v.z; s.w += v.w;
    }
    *(float4*)(dst + (size_t)b * MD + r4) = s;
}

// ===========================================================================
// launch
// ===========================================================================
extern "C" void kernel_launch(void* const* d_in, const int* in_sizes, int n_in,
                              void* d_out, int out_size) {
    const float* x   = (const float*)d_in[0];
    const float* act = (const float*)d_in[1];
    const float* W   = (const float*)d_in[2];

    float* out       = (float*)d_out;
    float* out_ncv   = out;
    float* out_q     = out + (size_t)BB * MM * DOUTD;
    float* out_route = out_q + (size_t)BB * NIN * MM;

    cudaFuncSetAttribute(votes_f16_kernel, cudaFuncAttributeMaxDynamicSharedMemorySize, VSMEM);
    cudaFuncSetAttribute(route_iter_kernel, cudaFuncAttributeMaxDynamicSharedMemorySize, ITER_SMEM);

    prep_x_kernel<<<XF4 / 256, 256>>>(x);
    votes_f16_kernel<<<dim3(MD / BNV, BB / BMV), 256, VSMEM>>>(W);

    route_iter_kernel<<<dim3(BB, NCHUNK), 256, ITER_SMEM>>>(act, 0, nullptr, nullptr);
    reduce_kernel<<<(BB * MD / 4) / 256, 256>>>(0, nullptr);
    route_iter_kernel<<<dim3(BB, NCHUNK), 256, ITER_SMEM>>>(act, 0, nullptr, nullptr);
    reduce_kernel<<<(BB * MD / 4) / 256, 256>>>(0, nullptr);
    route_iter_kernel<<<dim3(BB, NCHUNK), 256, ITER_SMEM>>>(act, 1, out_q, out_route);
    reduce_kernel<<<(BB * MD / 4) / 256, 256>>>(1, out_ncv);
}

// round 17
// speedup vs baseline: 1.1015x; 1.0208x over previous
#include <cuda_runtime.h>
#include <cuda_fp16.h>
#include <cstdint>

// Problem dims
#define BB    256
#define NIN   64
#define DIN   128
#define MM    32
#define DOUTD 128
#define MD    (MM * DOUTD)          // 4096
#define VPB   (NIN * MD)            // 262144
#define SCALE 0.08838834764831845f  // 1/sqrt(128)
#define NCHUNK 4
#define NPC   (NIN / NCHUNK)        // 16

// -------- device scratch ---------------------------------------------------
__device__ float g_votes[(size_t)BB * NIN * MM * DOUTD];     // 256 MiB
__device__ float g_ncv[(size_t)BB * MD];                     // 4 MiB
__device__ float g_part[(size_t)BB * NCHUNK * MD];           // 16 MiB
__device__ __half g_xh[(size_t)BB * NIN * DIN];              // 4 MiB  (fp16 x)
__device__ __half g_wh[(size_t)NIN * DIN * MD];              // 64 MiB (fp16 W)

// -------- helpers ------------------------------------------------------------
__device__ __forceinline__ void cp_async16(void* smem_dst, const void* gmem_src) {
    unsigned s = (unsigned)__cvta_generic_to_shared(smem_dst);
    asm volatile("cp.async.cg.shared.global [%0], [%1], 16;\n" :: "r"(s), "l"(gmem_src));
}
__device__ __forceinline__ void cp_async16s(uint32_t saddr, const void* gmem_src) {
    asm volatile("cp.async.cg.shared.global [%0], [%1], 16;\n" :: "r"(saddr), "l"(gmem_src));
}
__device__ __forceinline__ void cp_commit() { asm volatile("cp.async.commit_group;\n"); }
template <int N> __device__ __forceinline__ void cp_wait() {
    asm volatile("cp.async.wait_group %0;\n" :: "n"(N));
}

// pack two f32 -> f16x2 (lo = second operand)
#define F16X2(d, hi, lo) \
    asm("cvt.rn.f16x2.f32 %0, %1, %2;" : "=r"(d) : "f"(hi), "f"(lo))

#define MMA_F16(c0, c1, c2, c3, a0, a1, a2, a3, b0, b1)                        \
    asm volatile(                                                              \
        "mma.sync.aligned.m16n8k16.row.col.f32.f16.f16.f32 "                   \
        "{%0,%1,%2,%3}, {%4,%5,%6,%7}, {%8,%9}, {%0,%1,%2,%3};\n"              \
        : "+f"(c0), "+f"(c1), "+f"(c2), "+f"(c3)                               \
        : "r"(a0), "r"(a1), "r"(a2), "r"(a3), "r"(b0), "r"(b1))

#define LDSM_X4(r0, r1, r2, r3, addr)                                          \
    asm volatile(                                                              \
        "ldmatrix.sync.aligned.m8n8.x4.shared.b16 {%0,%1,%2,%3}, [%4];"        \
        : "=r"(r0), "=r"(r1), "=r"(r2), "=r"(r3) : "r"(addr))

#define LDSM_X4T(r0, r1, r2, r3, addr)                                         \
    asm volatile(                                                              \
        "ldmatrix.sync.aligned.m8n8.x4.trans.shared.b16 {%0,%1,%2,%3}, [%4];"  \
        : "=r"(r0), "=r"(r1), "=r"(r2), "=r"(r3) : "r"(addr))

// ===========================================================================
// K0a: convert x to fp16 (k-contiguous). ~3 us.
// K0b: convert W to fp16 (same layout [n][k][j]). 134 MB + 67 MB, ~30 us.
//      Bit-identical math to R16's in-register cvt — rel_err must not move.
// ===========================================================================
#define XF4 ((BB * NIN * DIN) / 4)        // 524,288
#define WF4 ((NIN * DIN * MD) / 4)        // 8,388,608

__global__ __launch_bounds__(256) void prep_x_kernel(const float* __restrict__ x) {
    const int idx = blockIdx.x * 256 + threadIdx.x;
    float4 v = ((const float4*)x)[idx];
    uint2 o;
    F16X2(o.x, v.y, v.x);
    F16X2(o.y, v.w, v.z);
    ((uint2*)g_xh)[idx] = o;
}

__global__ __launch_bounds__(256) void prep_w_kernel(const float* __restrict__ W) {
    const int idx = blockIdx.x * 256 + threadIdx.x;
    float4 v = ((const float4*)W)[idx];
    uint2 o;
    F16X2(o.x, v.y, v.x);
    F16X2(o.y, v.w, v.z);
    ((uint2*)g_wh)[idx] = o;
}

// ===========================================================================
// K1: votes via fp16 m16n8k16, fully ldmatrix-fed. Fused ncv0.
// 256 threads / 8 warps (4m x 2n), warp tile 32x32, block 128(b) x 64(j).
// Mainloop per ks: 2 A-LDSM.x4 + 2 B-LDSM.x4.trans + 8 MMA = 12 issues.
// ===========================================================================
#define BMV 128
#define BNV 64
#define APB 272                     // A row bytes (256 data + 16 pad)
#define BPB 144                     // B row bytes (128 data + 16 pad)
#define ABYTES (BMV * APB)          // 34,816
#define BBYTES (DIN * BPB)          // 18,432
#define STG_B  (ABYTES + BBYTES)    // 53,248
#define VSMEM  (2 * STG_B)          // 106,496 B

__global__ __launch_bounds__(256) void votes_f16_kernel() {
    extern __shared__ char sm_[];
    char* A0 = sm_;
    char* Bs0 = sm_ + ABYTES;
    char* A1 = sm_ + STG_B;
    char* Bs1 = sm_ + STG_B + ABYTES;

    const int j0 = blockIdx.x * BNV;
    const int b0 = blockIdx.y * BMV;
    const int tid  = threadIdx.x;
    const int lane = tid & 31;
    const int warp = tid >> 5;
    const int warp_m = warp >> 1;    // 0..3 (32 rows each)
    const int warp_n = warp & 1;     // 0..1 (32 cols each)
    const int g = lane >> 2;         // 0..7
    const int t = lane & 3;          // 0..3

    // A ldmatrix lane addressing (validated in R16):
    const int lrow = ((lane >> 3) & 1) * 8 + (lane & 7);
    const int koff = (lane >> 4) * 16;   // bytes
    const uint32_t a0base = (uint32_t)__cvta_generic_to_shared(A0)
                          + (uint32_t)((warp_m * 32 + lrow) * APB + koff);
    const uint32_t a1base = (uint32_t)__cvta_generic_to_shared(A1)
                          + (uint32_t)((warp_m * 32 + lrow) * APB + koff);

    // B ldmatrix.trans lane addressing:
    // x4 matrices: m0=[k0-7][j0-7], m1=[k8-15][j0-7], m2=[k0-7][j8-15], m3=[k8-15][j8-15]
    const int sel  = lane >> 3;          // 0..3
    const int kadd = (sel & 1) * 8;      // k-row offset within ks
    const int jadd = (sel >> 1) * 16;    // bytes (8 halves)
    const int brow = lane & 7;
    const uint32_t b0base = (uint32_t)__cvta_generic_to_shared(Bs0)
                          + (uint32_t)((kadd + brow) * BPB + warp_n * 64 + jadd);
    const uint32_t b1base = (uint32_t)__cvta_generic_to_shared(Bs1)
                          + (uint32_t)((kadd + brow) * BPB + warp_n * 64 + jadd);

    const __half* xbase = g_xh + (size_t)b0 * (NIN * DIN);
    const __half* wbase = g_wh + j0;

    auto issue_tile = [&](char* Ad, char* Bd, int n) {
        const __half* xs = xbase + n * DIN;
        const uint32_t adst = (uint32_t)__cvta_generic_to_shared(Ad);
        #pragma unroll
        for (int i = 0; i < 8; ++i) {             // A: 128 rows x 16 chunks (16B)
            int id = tid + i * 256;
            int r = id >> 4, c = id & 15;
            cp_async16s(adst + (uint32_t)(r * APB + c * 16),
                        xs + (size_t)r * (NIN * DIN) + c * 8);
        }
        const __half* ws = wbase + (size_t)n * (DIN * MD);
        const uint32_t bdst = (uint32_t)__cvta_generic_to_shared(Bd);
        #pragma unroll
        for (int i = 0; i < 4; ++i) {             // B: 128 k-rows x 8 chunks (16B)
            int id = tid + i * 256;
            int r = id >> 3, c = id & 7;
            cp_async16s(bdst + (uint32_t)(r * BPB + c * 16),
                        ws + (size_t)r * MD + c * 8);
        }
        cp_commit();
    };

    float c[2][4][4];
    float ncv[2][4][4];
    #pragma unroll
    for (int mt = 0; mt < 2; ++mt)
        #pragma unroll
        for (int nt = 0; nt < 4; ++nt)
            #pragma unroll
            for (int qq = 0; qq < 4; ++qq) { c[mt][nt][qq] = 0.f; ncv[mt][nt][qq] = 0.f; }

    issue_tile(A0, Bs0, 0);

    for (int n = 0; n < NIN; ++n) {
        const uint32_t abase = (n & 1) ? a1base : a0base;
        const uint32_t bbase = (n & 1) ? b1base : b0base;
        if (n + 1 < NIN) {
            issue_tile((n & 1) ? A0 : A1, (n & 1) ? Bs0 : Bs1, n + 1);
            cp_wait<1>();
        } else {
            cp_wait<0>();
        }
        __syncthreads();

        // ---- mainloop: 8 k-steps of 16
        #pragma unroll
        for (int ks = 0; ks < 8; ++ks) {
            uint32_t a0_[4], a1_[4], bA[4], bB[4];
            LDSM_X4(a0_[0], a0_[1], a0_[2], a0_[3], abase + ks * 32);
            LDSM_X4(a1_[0], a1_[1], a1_[2], a1_[3], abase + 16 * APB + ks * 32);
            LDSM_X4T(bA[0], bA[1], bA[2], bA[3], bbase + ks * 16 * BPB);        // nt0, nt1
            LDSM_X4T(bB[0], bB[1], bB[2], bB[3], bbase + ks * 16 * BPB + 32);   // nt2, nt3
            #pragma unroll
            for (int mt = 0; mt < 2; ++mt) {
                uint32_t* am = mt ? a1_ : a0_;
                MMA_F16(c[mt][0][0], c[mt][0][1], c[mt][0][2], c[mt][0][3],
                        am[0], am[1], am[2], am[3], bA[0], bA[1]);
                MMA_F16(c[mt][1][0], c[mt][1][1], c[mt][1][2], c[mt][1][3],
                        am[0], am[1], am[2], am[3], bA[2], bA[3]);
                MMA_F16(c[mt][2][0], c[mt][2][1], c[mt][2][2], c[mt][2][3],
                        am[0], am[1], am[2], am[3], bB[0], bB[1]);
                MMA_F16(c[mt][3][0], c[mt][3][1], c[mt][3][2], c[mt][3][3],
                        am[0], am[1], am[2], am[3], bB[2], bB[3]);
            }
        }

        // ---- epilogue: write votes tile, accumulate ncv, reset c
        #pragma unroll
        for (int mt = 0; mt < 2; ++mt) {
            const int row = warp_m * 32 + mt * 16 + g;
            float* vp = g_votes + (size_t)(b0 + row) * VPB + (size_t)n * MD + j0;
            #pragma unroll
            for (int nt = 0; nt < 4; ++nt) {
                const int col = warp_n * 32 + nt * 8 + 2 * t;
                *(float2*)(vp + col)           = make_float2(c[mt][nt][0], c[mt][nt][1]);
                *(float2*)(vp + 8 * VPB + col) = make_float2(c[mt][nt][2], c[mt][nt][3]);
                ncv[mt][nt][0] += c[mt][nt][0]; c[mt][nt][0] = 0.f;
                ncv[mt][nt][1] += c[mt][nt][1]; c[mt][nt][1] = 0.f;
                ncv[mt][nt][2] += c[mt][nt][2]; c[mt][nt][2] = 0.f;
                ncv[mt][nt][3] += c[mt][nt][3]; c[mt][nt][3] = 0.f;
            }
        }
        __syncthreads();   // protect smem buffers before next prefetch overwrite
    }

    // ---- write ncv0 = (1/M) * sum_n votes (fused)
    #pragma unroll
    for (int mt = 0; mt < 2; ++mt) {
        const int row = warp_m * 32 + mt * 16 + g;
        float* np = g_ncv + (size_t)(b0 + row) * MD + j0;
        #pragma unroll
        for (int nt = 0; nt < 4; ++nt) {
            const int col = warp_n * 32 + nt * 8 + 2 * t;
            *(float2*)(np + col) =
                make_float2(ncv[mt][nt][0] * (1.0f / MM), ncv[mt][nt][1] * (1.0f / MM));
            *(float2*)(np + 8 * MD + col) =
                make_float2(ncv[mt][nt][2] * (1.0f / MM), ncv[mt][nt][3] * (1.0f / MM));
        }
    }
}

// ===========================================================================
// K3: routing iteration, n-chunked. grid (BB, NCHUNK=4). (R13 verbatim.)
// ===========================================================================
#define ITER_SMEM ((MD + 2 * MD + 32) * 4)   // 49,280 B

__global__ __launch_bounds__(256) void route_iter_kernel(const float* __restrict__ act,
                                                         int is_final,
                                                         float* __restrict__ out_q,
                                                         float* __restrict__ out_route) {
    extern __shared__ float smem[];
    float* s_ncv   = smem;
    float* s_votes = smem + MD;
    float* s_q     = smem + 3 * MD;

    const int b     = blockIdx.x;
    const int chunk = blockIdx.y;
    const int n0    = chunk * NPC;
    const int tid  = threadIdx.x;
    const int lane = tid & 31;
    const int warp = tid >> 5;

    #pragma unroll 4
    for (int i = tid; i < MD; i += 256) s_ncv[i] = g_ncv[(size_t)b * MD + i];

    float4 acc0 = make_float4(0.f, 0.f, 0.f, 0.f);
    float4 acc1 = make_float4(0.f, 0.f, 0.f, 0.f);
    float4 acc2 = make_float4(0.f, 0.f, 0.f, 0.f);
    float4 acc3 = make_float4(0.f, 0.f, 0.f, 0.f);

    const float* vbase = g_votes + (size_t)b * VPB + (size_t)n0 * MD;

    #pragma unroll
    for (int i = tid * 4; i < MD; i += 1024) cp_async16(&s_votes[i], vbase + i);
    cp_commit();

    for (int nn = 0; nn < NPC; ++nn) {
        const int n = n0 + nn;
        const int buf = (nn & 1) * MD;
        if (nn + 1 < NPC) {
            const float* src = vbase + (size_t)(nn + 1) * MD;
            const int nbuf = ((nn + 1) & 1) * MD;
            #pragma unroll
            for (int i = tid * 4; i < MD; i += 1024) cp_async16(&s_votes[nbuf + i], src + i);
            cp_commit();
            cp_wait<1>();
        } else {
            cp_wait<0>();
        }
        __syncthreads();

        #pragma unroll
        for (int j = 0; j < 4; ++j) {
            const int m = warp * 4 + j;
            const float* vr = &s_votes[buf + m * DOUTD];
            const float* cr = &s_ncv[m * DOUTD];
            float p = vr[lane]      * cr[lane]
                    + vr[lane + 32] * cr[lane + 32]
                    + vr[lane + 64] * cr[lane + 64]
                    + vr[lane + 96] * cr[lane + 96];
            p += __shfl_xor_sync(0xffffffffu, p, 16);
            p += __shfl_xor_sync(0xffffffffu, p, 8);
            p += __shfl_xor_sync(0xffffffffu, p, 4);
            p += __shfl_xor_sync(0xffffffffu, p, 2);
            p += __shfl_xor_sync(0xffffffffu, p, 1);
            if (lane == 0) s_q[m] = p;
        }
        __syncthreads();

        if (warp == 0) {
            float v = s_q[lane] * SCALE;
            float mx = v;
            #pragma unroll
            for (int o = 16; o > 0; o >>= 1) mx = fmaxf(mx, __shfl_xor_sync(0xffffffffu, mx, o));
            float e = expf(v - mx);
            float sm = e;
            #pragma unroll
            for (int o = 16; o > 0; o >>= 1) sm += __shfl_xor_sync(0xffffffffu, sm, o);
            s_q[lane] = e / sm;
        }
        __syncthreads();

        const float wa = act[b * NIN + n];
        {
            const int i0 = tid * 4;
            float q0 = s_q[i0 >> 7] * wa;
            float q1 = s_q[(i0 + 1024) >> 7] * wa;
            float q2 = s_q[(i0 + 2048) >> 7] * wa;
            float q3 = s_q[(i0 + 3072) >> 7] * wa;
            float4 v0 = *(const float4*)&s_votes[buf + i0];
            float4 v1 = *(const float4*)&s_votes[buf + i0 + 1024];
            float4 v2 = *(const float4*)&s_votes[buf + i0 + 2048];
            float4 v3 = *(const float4*)&s_votes[buf + i0 + 3072];
            v0.x *= q0; v0.y *= q0; v0.z *= q0; v0.w *= q0;
            v1.x *= q1; v1.y *= q1; v1.z *= q1; v1.w *= q1;
            v2.x *= q2; v2.y *= q2; v2.z *= q2; v2.w *= q2;
            v3.x *= q3; v3.y *= q3; v3.z *= q3; v3.w *= q3;
            acc0.x += v0.x; acc0.y += v0.y; acc0.z += v0.z; acc0.w += v0.w;
            acc1.x += v1.x; acc1.y += v1.y; acc1.z += v1.z; acc1.w += v1.w;
            acc2.x += v2.x; acc2.y += v2.y; acc2.z += v2.z; acc2.w += v2.w;
            acc3.x += v3.x; acc3.y += v3.y; acc3.z += v3.z; acc3.w += v3.w;
            if (is_final) {
                float* rp = out_route + (size_t)b * VPB + (size_t)n * MD;
                *(float4*)(rp + i0)        = v0;
                *(float4*)(rp + i0 + 1024) = v1;
                *(float4*)(rp + i0 + 2048) = v2;
                *(float4*)(rp + i0 + 3072) = v3;
            }
        }
        if (is_final && tid < MM)
            out_q[(size_t)b * (NIN * MM) + n * MM + tid] = s_q[tid];
        __syncthreads();
    }

    float* pp = g_part + ((size_t)b * NCHUNK + chunk) * MD;
    const int i0 = tid * 4;
    *(float4*)(pp + i0)        = acc0;
    *(float4*)(pp + i0 + 1024) = acc1;
    *(float4*)(pp + i0 + 2048) = acc2;
    *(float4*)(pp + i0 + 3072) = acc3;
}

// ===========================================================================
// K4: reduce partials -> g_ncv (to_out=0) or out_ncv (to_out=1).
// ===========================================================================
__global__ __launch_bounds__(256) void reduce_kernel(int to_out, float* __restrict__ out_ncv) {
    float* dst = to_out ? out_ncv : g_ncv;
    const int idx = blockIdx.x * 256 + threadIdx.x;
    const int b  = idx >> 10;
    const int r4 = (idx & 1023) * 4;
    const float* pp = g_part + (size_t)b * NCHUNK * MD + r4;
    float4 s = make_float4(0.f, 0.f, 0.f, 0.f);
    #pragma unroll 4
    for (int c = 0; c < NCHUNK; ++c) {
        float4 v = *(const float4*)(pp + (size_t)c * MD);
        s.x += v.x; s.y += v.y; s.z += v.z; s.w += v.w;
    }
    *(float4*)(dst + (size_t)b * MD + r4) = s;
}

// ===========================================================================
// launch
// ===========================================================================
extern "C" void kernel_launch(void* const* d_in, const int* in_sizes, int n_in,
                              void* d_out, int out_size) {
    const float* x   = (const float*)d_in[0];
    const float* act = (const float*)d_in[1];
    const float* W   = (const float*)d_in[2];

    float* out       = (float*)d_out;
    float* out_ncv   = out;
    float* out_q     = out + (size_t)BB * MM * DOUTD;
    float* out_route = out_q + (size_t)BB * NIN * MM;

    cudaFuncSetAttribute(votes_f16_kernel, cudaFuncAttributeMaxDynamicSharedMemorySize, VSMEM);
    cudaFuncSetAttribute(route_iter_kernel, cudaFuncAttributeMaxDynamicSharedMemorySize, ITER_SMEM);

    prep_x_kernel<<<XF4 / 256, 256>>>(x);
    prep_w_kernel<<<WF4 / 256, 256>>>(W);
    votes_f16_kernel<<<dim3(MD / BNV, BB / BMV), 256, VSMEM>>>();

    route_iter_kernel<<<dim3(BB, NCHUNK), 256, ITER_SMEM>>>(act, 0, nullptr, nullptr);
    reduce_kernel<<<(BB * MD / 4) / 256, 256>>>(0, nullptr);
    route_iter_kernel<<<dim3(BB, NCHUNK), 256, ITER_SMEM>>>(act, 0, nullptr, nullptr);
    reduce_kernel<<<(BB * MD / 4) / 256, 256>>>(0, nullptr);
    route_iter_kernel<<<dim3(BB, NCHUNK), 256, ITER_SMEM>>>(act, 1, out_q, out_route);
    reduce_kernel<<<(BB * MD / 4) / 256, 256>>>(1, out_ncv);
}